// round 15
// baseline (speedup 1.0000x reference)
#include <cuda_runtime.h>
#include <cuda_bf16.h>
#include <cstdint>

#define Bz   4
#define Sz   4096
#define Hz   8
#define Lz   1024      // H * DI
#define N1z  384       // 3 * DO
#define NCH  128       // chunks over S
#define CLEN 32        // S / NCH
#define EPSf 1e-6f

typedef unsigned long long u64;

// ---------------- scratch (static device memory; no allocations) ----------------
static __device__ float  g_h3[(size_t)Bz * Sz * Hz * N1z];       // 192 MB
static __device__ float2 g_fgi[(size_t)Bz * Sz * Lz];            // 128 MB (f, i)
static __device__ float  g_og[(size_t)Bz * Sz * Lz];             // 64 MB
static __device__ float  g_chA[Bz * NCH * Lz];
static __device__ float  g_chF[Bz * NCH * Lz];
static __device__ float  g_chAcc[Bz * NCH * Lz];
static __device__ float  g_carry[Bz * NCH * Lz];
// split-bf16 A-side operand planes, layout [m][h][k] (k fastest, 128 per head)
static __device__ __nv_bfloat16 g_x_hi[(size_t)Bz * Sz * Lz];
static __device__ __nv_bfloat16 g_x_lo[(size_t)Bz * Sz * Lz];
static __device__ __nv_bfloat16 g_csum_hi[(size_t)Bz * Sz * Lz];
static __device__ __nv_bfloat16 g_csum_lo[(size_t)Bz * Sz * Lz];
static __device__ __nv_bfloat16 g_cell_hi[(size_t)Bz * Sz * Lz];
static __device__ __nv_bfloat16 g_cell_lo[(size_t)Bz * Sz * Lz];
// split-bf16 weights, transposed to [h][n][k=256]
static __device__ __nv_bfloat16 g_Whid_hi[Hz * N1z * 256];
static __device__ __nv_bfloat16 g_Whid_lo[Hz * N1z * 256];
static __device__ __nv_bfloat16 g_Wog_hi[Hz * 128 * 256];
static __device__ __nv_bfloat16 g_Wog_lo[Hz * 128 * 256];

// ========================= asm helpers ==========================
__device__ __forceinline__ uint32_t smem_u32(const void* p) {
    uint32_t a;
    asm("{ .reg .u64 t; cvta.to.shared.u64 t, %1; cvt.u32.u64 %0, t; }"
        : "=r"(a) : "l"(p));
    return a;
}
__device__ __forceinline__ void ldsm4(uint32_t* r, uint32_t addr) {
    asm volatile("ldmatrix.sync.aligned.m8n8.x4.shared.b16 {%0,%1,%2,%3}, [%4];"
        : "=r"(r[0]), "=r"(r[1]), "=r"(r[2]), "=r"(r[3]) : "r"(addr));
}
__device__ __forceinline__ void mma16816(float* c, const uint32_t* a, const uint32_t* b) {
    asm volatile(
        "mma.sync.aligned.m16n8k16.row.col.f32.bf16.bf16.f32 "
        "{%0,%1,%2,%3}, {%4,%5,%6,%7}, {%8,%9}, {%0,%1,%2,%3};"
        : "+f"(c[0]), "+f"(c[1]), "+f"(c[2]), "+f"(c[3])
        : "r"(a[0]), "r"(a[1]), "r"(a[2]), "r"(a[3]), "r"(b[0]), "r"(b[1]));
}
__device__ __forceinline__ void cpa16(uint32_t dst, const void* src) {
    asm volatile("cp.async.cg.shared.global [%0], [%1], 16;" :: "r"(dst), "l"(src));
}
#define CP_COMMIT() asm volatile("cp.async.commit_group;")

// SW64 swizzle for 64-byte rows (conflict-free 8x16B ldmatrix)
__device__ __forceinline__ uint32_t swz64(uint32_t o) { return o ^ ((o >> 3) & 0x30); }

// stage layout: per stage 32KB = Ahi(8K) Alo(8K) Bhi(8K) Blo(8K); 3 stages = 96KB
#define STG(s)  ((s) * 32768)
#define P_AHI 0
#define P_ALO 8192
#define P_BHI 16384
#define P_BLO 24576
#define SM_TOT 98304

// =====================================================================
// Fused: Phase-1 chunk sums + x hi/lo split (single x read) | weight conv
// =====================================================================
__global__ void k_partial_wconv(const float* __restrict__ x,
                                const float* __restrict__ W_hid,
                                const float* __restrict__ W_og) {
    __shared__ __nv_bfloat16 smh[64][66];
    __shared__ __nv_bfloat16 sml[64][66];
    const int bx = blockIdx.x, by = blockIdx.y, tid = threadIdx.x;

    if (bx < Bz) {
        const size_t base = (size_t)(bx * Sz + by * CLEN) * Lz + tid;
        float s = 0.f;
        #pragma unroll 4
        for (int i = 0; i < CLEN; i++) {
            const float v = x[base + (size_t)i * Lz];
            s += v;
            const __nv_bfloat16 vh = __float2bfloat16(v);
            g_x_hi[base + (size_t)i * Lz] = vh;
            g_x_lo[base + (size_t)i * Lz] = __float2bfloat16(v - __bfloat162float(vh));
        }
        g_chA[(bx * NCH + by) * Lz + tid] = s;
        return;
    }

    // weight conversion tile
    const int t = (bx - Bz) * gridDim.y + by;   // 0..255
    const float* W;
    __nv_bfloat16 *hi, *lo;
    int N, h, kt, nt;
    if (t < 192) {
        W = W_hid; hi = g_Whid_hi; lo = g_Whid_lo; N = N1z;
        h = t / 24; const int r = t % 24; kt = r / 6; nt = r % 6;
    } else {
        const int t2 = t - 192;
        W = W_og; hi = g_Wog_hi; lo = g_Wog_lo; N = 128;
        h = t2 / 8; const int r = t2 % 8; kt = r / 2; nt = r % 2;
    }
    #pragma unroll
    for (int i = 0; i < 4; i++) {
        const int idx = tid + i * 1024;
        const int nl = idx & 63, kl = idx >> 6;
        const float v = W[(size_t)(h * 256 + kt * 64 + kl) * N + nt * 64 + nl];
        const __nv_bfloat16 vh = __float2bfloat16(v);
        smh[nl][kl] = vh;
        sml[nl][kl] = __float2bfloat16(v - __bfloat162float(vh));
    }
    __syncthreads();
    {
        const int nl = tid >> 4, k4 = (tid & 15) * 4;
        __nv_bfloat16 h4[4], l4[4];
        #pragma unroll
        for (int j = 0; j < 4; j++) { h4[j] = smh[nl][k4 + j]; l4[j] = sml[nl][k4 + j]; }
        const size_t o = (size_t)(h * N + nt * 64 + nl) * 256 + kt * 64 + k4;
        *(uint2*)(hi + o) = *(uint2*)h4;
        *(uint2*)(lo + o) = *(uint2*)l4;
    }
}

// =====================================================================
// Phase 1b: chunk-offset exclusive scan (MLP-batched loads)
// =====================================================================
__global__ void k_scan1_offsets() {
    const int b = blockIdx.x, l = threadIdx.x;
    float run = 0.f;
    #pragma unroll
    for (int g = 0; g < NCH; g += 16) {
        float v[16];
        #pragma unroll
        for (int j = 0; j < 16; j++)
            v[j] = g_chA[(b * NCH + g + j) * Lz + l];
        #pragma unroll
        for (int j = 0; j < 16; j++) {
            g_chA[(b * NCH + g + j) * Lz + l] = run;
            run += v[j];
        }
    }
}

// =====================================================================
// Phase 1c: cumsum + LN over 1024, batch-8 positions per reduction round
// =====================================================================
__global__ void k_scan1_ln(const float* __restrict__ x,
                           const float* __restrict__ gam,
                           const float* __restrict__ bet) {
    __shared__ float sred1[8][32];
    __shared__ float sred2[8][32];
    __shared__ float s_stats[8][2];
    const int b = blockIdx.x, ch = blockIdx.y, l = threadIdx.x;
    const int wid = l >> 5, lane = l & 31;
    float c = g_chA[(b * NCH + ch) * Lz + l];
    const float gv = gam[l], bv = bet[l];
    const size_t base = (size_t)(b * Sz + ch * CLEN) * Lz + l;

    for (int i0 = 0; i0 < CLEN; i0 += 8) {
        float v[8];
        {
            float run = c;
            #pragma unroll
            for (int p = 0; p < 8; p++) {
                v[p] = run;
                run += x[base + (size_t)(i0 + p) * Lz];
            }
            c = run;
        }
        float r1[8], r2[8];
        #pragma unroll
        for (int p = 0; p < 8; p++) { r1[p] = v[p]; r2[p] = v[p] * v[p]; }
        #pragma unroll
        for (int off = 16; off > 0; off >>= 1)
            #pragma unroll
            for (int p = 0; p < 8; p++) {
                r1[p] += __shfl_down_sync(0xffffffffu, r1[p], off);
                r2[p] += __shfl_down_sync(0xffffffffu, r2[p], off);
            }
        if (lane == 0)
            #pragma unroll
            for (int p = 0; p < 8; p++) { sred1[p][wid] = r1[p]; sred2[p][wid] = r2[p]; }
        __syncthreads();
        if (wid < 8) {
            float t1 = sred1[wid][lane], t2 = sred2[wid][lane];
            #pragma unroll
            for (int off = 16; off > 0; off >>= 1) {
                t1 += __shfl_down_sync(0xffffffffu, t1, off);
                t2 += __shfl_down_sync(0xffffffffu, t2, off);
            }
            if (lane == 0) {
                const float mu = t1 * (1.f / 1024.f);
                s_stats[wid][0] = mu;
                s_stats[wid][1] = rsqrtf(t2 * (1.f / 1024.f) - mu * mu + EPSf);
            }
        }
        __syncthreads();
        #pragma unroll
        for (int p = 0; p < 8; p++) {
            const float ov = (v[p] - s_stats[p][0]) * s_stats[p][1] * gv + bv;
            const __nv_bfloat16 oh = __float2bfloat16(ov);
            g_csum_hi[base + (size_t)(i0 + p) * Lz] = oh;
            g_csum_lo[base + (size_t)(i0 + p) * Lz] =
                __float2bfloat16(ov - __bfloat162float(oh));
        }
        __syncthreads();
    }
}

// =====================================================================
// Fully-async HMMA GEMM: K-chunks of 32, 3-stage cp.async ring (96KB),
// 2 CTAs/SM, single sync per chunk, term-major MMA ordering.
// PHASE1 grid: (n=3, m=128, h=8) so n-tile siblings sharing A run
// temporally adjacent -> A reads hit L2.  GEMM2 grid: (m, 1, h).
// =====================================================================
template <int NLD, bool PHASE1>
__global__ __launch_bounds__(256, 2) void k_gemm_pipe(const float* __restrict__ bias) {
    float* __restrict__ C = PHASE1 ? g_h3 : g_og;
    const __nv_bfloat16* __restrict__ Bhi = PHASE1 ? g_Whid_hi : g_Wog_hi;
    const __nv_bfloat16* __restrict__ Blo = PHASE1 ? g_Whid_lo : g_Wog_lo;
    const __nv_bfloat16* __restrict__ A1hi = PHASE1 ? g_csum_hi : g_cell_hi;
    const __nv_bfloat16* __restrict__ A1lo = PHASE1 ? g_csum_lo : g_cell_lo;

    extern __shared__ char sm[];
    const uint32_t sb = smem_u32(sm);
    const int tid = threadIdx.x;
    const int lane = tid & 31, wid = tid >> 5;
    const int m0 = (PHASE1 ? blockIdx.y : blockIdx.x) * 128;
    const int n0 = (PHASE1 ? blockIdx.x : blockIdx.y) * 128;
    const int h  = blockIdx.z;
    const int wm = (wid & 3) * 32;
    const int wn = (wid >> 2) * 64;

    float acc[2][8][4];
    #pragma unroll
    for (int mt = 0; mt < 2; mt++)
        #pragma unroll
        for (int nt = 0; nt < 8; nt++)
            #pragma unroll
            for (int q = 0; q < 4; q++) acc[mt][nt][q] = 0.f;

    const int aq = lane >> 3;
    const int arow_l = (aq & 1) * 8 + (lane & 7);
    const int akb    = (aq >> 1) * 16;
    const int brow_l = (aq >> 1) * 8 + (lane & 7);
    const int bkb    = (aq & 1) * 16;

    // stage s covers k elements [s*32, s*32+32); ring slot s%3
    #define ISSUE_STAGE(s) do {                                                    \
        const __nv_bfloat16* Ah = ((s) < 4) ? g_x_hi : A1hi;                       \
        const __nv_bfloat16* Al = ((s) < 4) ? g_x_lo : A1lo;                       \
        const int kA = ((s) & 3) * 32;                                             \
        const uint32_t stb = sb + STG((s) % 3);                                    \
        _Pragma("unroll")                                                          \
        for (int j = 0; j < 2; j++) {                                              \
            const int idx = tid + j * 256;                                         \
            const int row = idx >> 2, q = idx & 3;                                 \
            const uint32_t so = swz64((uint32_t)(row * 64 + q * 16));              \
            const size_t aoff = ((size_t)(m0 + row) * Hz + h) * 128 + kA + q * 8;  \
            cpa16(stb + P_AHI + so, Ah + aoff);                                    \
            cpa16(stb + P_ALO + so, Al + aoff);                                    \
            const size_t boff = ((size_t)(h * NLD + n0 + row) * 256 + (s) * 32 + q * 8); \
            cpa16(stb + P_BHI + so, Bhi + boff);                                   \
            cpa16(stb + P_BLO + so, Blo + boff);                                   \
        }                                                                          \
        CP_COMMIT();                                                               \
    } while (0)

    ISSUE_STAGE(0);
    ISSUE_STAGE(1);

    #pragma unroll 1
    for (int c = 0; c < 8; c++) {
        if (c < 7) asm volatile("cp.async.wait_group 1;");
        else       asm volatile("cp.async.wait_group 0;");
        __syncthreads();
        // slot (c+2)%3 == (c-1)%3: fully consumed by all warps before this sync
        if (c + 2 < 8) ISSUE_STAGE(c + 2);

        const uint32_t stb = sb + STG(c % 3);
        #pragma unroll
        for (int k16 = 0; k16 < 2; k16++) {
            uint32_t ahi[2][4], alo[2][4];
            #pragma unroll
            for (int mt = 0; mt < 2; mt++) {
                const uint32_t off =
                    swz64((uint32_t)((wm + mt * 16 + arow_l) * 64 + k16 * 32 + akb));
                ldsm4(ahi[mt], stb + P_AHI + off);
                ldsm4(alo[mt], stb + P_ALO + off);
            }
            #pragma unroll
            for (int np = 0; np < 4; np++) {
                uint32_t bhi[4], blo[4];
                const uint32_t off =
                    swz64((uint32_t)((wn + np * 16 + brow_l) * 64 + k16 * 32 + bkb));
                ldsm4(bhi, stb + P_BHI + off);
                ldsm4(blo, stb + P_BLO + off);
                // term-major: 4 independent accumulators between reuses
                float* a00 = acc[0][np * 2];
                float* a01 = acc[0][np * 2 + 1];
                float* a10 = acc[1][np * 2];
                float* a11 = acc[1][np * 2 + 1];
                mma16816(a00, ahi[0], bhi);
                mma16816(a01, ahi[0], bhi + 2);
                mma16816(a10, ahi[1], bhi);
                mma16816(a11, ahi[1], bhi + 2);
                mma16816(a00, alo[0], bhi);
                mma16816(a01, alo[0], bhi + 2);
                mma16816(a10, alo[1], bhi);
                mma16816(a11, alo[1], bhi + 2);
                mma16816(a00, ahi[0], blo);
                mma16816(a01, ahi[0], blo + 2);
                mma16816(a10, ahi[1], blo);
                mma16816(a11, ahi[1], blo + 2);
            }
        }
    }

    // ---- epilogue ----
    #pragma unroll
    for (int mt = 0; mt < 2; mt++) {
        const int r0 = m0 + wm + mt * 16 + (lane >> 2);
        #pragma unroll
        for (int nt = 0; nt < 8; nt++) {
            const int col = n0 + wn + nt * 8 + (lane & 3) * 2;
            const float2 bv = *(const float2*)(bias + h * NLD + col);
            float2 o0, o1;
            o0.x = acc[mt][nt][0] + bv.x;  o0.y = acc[mt][nt][1] + bv.y;
            o1.x = acc[mt][nt][2] + bv.x;  o1.y = acc[mt][nt][3] + bv.y;
            *(float2*)(C + ((size_t)r0 * Hz + h) * NLD + col)       = o0;
            *(float2*)(C + ((size_t)(r0 + 8) * Hz + h) * NLD + col) = o1;
        }
    }
    #undef ISSUE_STAGE
}

// =====================================================================
// Phase 3: LN over 3072 + gates + chunk composition, batch-8 positions
// =====================================================================
__global__ void k_gates(const float* __restrict__ gam, const float* __restrict__ bet) {
    __shared__ float sred1[8][32];
    __shared__ float sred2[8][32];
    __shared__ float s_stats[8][2];
    const int b = blockIdx.x, ch = blockIdx.y, l = threadIdx.x;
    const int wid = l >> 5, lane = l & 31;
    const int h = l >> 7, dd = l & 127;
    const int pb = (h * 3) * 128 + dd;
    const int rbase = h * N1z + dd;                 // channel of igate in row
    const float gi = gam[pb], gf = gam[pb + 128], gh = gam[pb + 256];
    const float bi = bet[pb], bf = bet[pb + 128], bh = bet[pb + 256];
    float F = 1.f, Acc = 0.f;

    for (int i0 = 0; i0 < CLEN; i0 += 8) {
        float vi[8], vf[8], vh[8];
        #pragma unroll
        for (int p = 0; p < 8; p++) {
            const size_t rb = (size_t)(b * Sz + ch * CLEN + i0 + p) * (Hz * N1z) + rbase;
            vi[p] = g_h3[rb];
            vf[p] = g_h3[rb + 128];
            vh[p] = g_h3[rb + 256];
        }
        float r1[8], r2[8];
        #pragma unroll
        for (int p = 0; p < 8; p++) {
            r1[p] = vi[p] + vf[p] + vh[p];
            r2[p] = vi[p] * vi[p] + vf[p] * vf[p] + vh[p] * vh[p];
        }
        #pragma unroll
        for (int off = 16; off > 0; off >>= 1)
            #pragma unroll
            for (int p = 0; p < 8; p++) {
                r1[p] += __shfl_down_sync(0xffffffffu, r1[p], off);
                r2[p] += __shfl_down_sync(0xffffffffu, r2[p], off);
            }
        if (lane == 0)
            #pragma unroll
            for (int p = 0; p < 8; p++) { sred1[p][wid] = r1[p]; sred2[p][wid] = r2[p]; }
        __syncthreads();
        if (wid < 8) {
            float t1 = sred1[wid][lane], t2 = sred2[wid][lane];
            #pragma unroll
            for (int off = 16; off > 0; off >>= 1) {
                t1 += __shfl_down_sync(0xffffffffu, t1, off);
                t2 += __shfl_down_sync(0xffffffffu, t2, off);
            }
            if (lane == 0) {
                const float mu = t1 * (1.f / 3072.f);
                s_stats[wid][0] = mu;
                s_stats[wid][1] = rsqrtf(t2 * (1.f / 3072.f) - mu * mu + EPSf);
            }
        }
        __syncthreads();
        #pragma unroll
        for (int p = 0; p < 8; p++) {
            const float mu = s_stats[p][0], rs = s_stats[p][1];
            const float xig = (vi[p] - mu) * rs * gi + bi;
            const float xfg = (vf[p] - mu) * rs * gf + bf;
            const float xhd = (vh[p] - mu) * rs * gh + bh;
            const float f  = 1.f / (1.f + __expf(-xfg));
            const float ii = (1.f / (1.f + __expf(-xig))) * fmaxf(xhd, 0.f);
            g_fgi[(size_t)(b * Sz + ch * CLEN + i0 + p) * Lz + l] = make_float2(f, ii);
            Acc = f * Acc + ii;
            F *= f;
        }
        __syncthreads();
    }
    const int ci = (b * NCH + ch) * Lz + l;
    g_chF[ci] = F;
    g_chAcc[ci] = Acc;
}

// =====================================================================
// Phase 4a: chunk-carry scan (MLP-batched loads)
// =====================================================================
__global__ void k_carry(const float* __restrict__ init_cx) {
    const int b = blockIdx.x, l = threadIdx.x;
    float c = init_cx[l];
    #pragma unroll
    for (int g = 0; g < NCH; g += 16) {
        float vf[16], va[16];
        #pragma unroll
        for (int j = 0; j < 16; j++) {
            const int idx = (b * NCH + g + j) * Lz + l;
            vf[j] = g_chF[idx];
            va[j] = g_chAcc[idx];
        }
        #pragma unroll
        for (int j = 0; j < 16; j++) {
            g_carry[(b * NCH + g + j) * Lz + l] = c;
            c = vf[j] * c + va[j];
        }
    }
}

// =====================================================================
// Phase 4b: replay scan, writing cell as split-bf16 planes
// =====================================================================
__global__ void k_replay() {
    const int b = blockIdx.x, ch = blockIdx.y, l = threadIdx.x;
    float c = g_carry[(b * NCH + ch) * Lz + l];
    const size_t base = (size_t)(b * Sz + ch * CLEN) * Lz + l;
    #pragma unroll 8
    for (int i = 0; i < CLEN; i++) {
        const float2 fi = g_fgi[base + (size_t)i * Lz];
        c = fi.x * c + fi.y;
        const __nv_bfloat16 chh = __float2bfloat16(c);
        g_cell_hi[base + (size_t)i * Lz] = chh;
        g_cell_lo[base + (size_t)i * Lz] = __float2bfloat16(c - __bfloat162float(chh));
    }
}

// =====================================================================
// Phase 5: LN over (H,DO) per (b,s), sigmoid(og) * cell -> out
// =====================================================================
__global__ void k_final(const float* __restrict__ gam, const float* __restrict__ bet,
                        float* __restrict__ out) {
    __shared__ float sred[16];
    __shared__ float s_stats[2];
    const int bs = blockIdx.x, t = threadIdx.x;
    const int wid = t >> 5, lane = t & 31;
    const size_t base = (size_t)bs * Lz + t * 4;
    const float4 v = *(const float4*)(g_og + base);
    float r1 = v.x + v.y + v.z + v.w;
    float r2 = v.x * v.x + v.y * v.y + v.z * v.z + v.w * v.w;
    #pragma unroll
    for (int off = 16; off > 0; off >>= 1) {
        r1 += __shfl_down_sync(0xffffffffu, r1, off);
        r2 += __shfl_down_sync(0xffffffffu, r2, off);
    }
    if (lane == 0) { sred[wid] = r1; sred[8 + wid] = r2; }
    __syncthreads();
    if (wid == 0) {
        float t1 = lane < 8 ? sred[lane] : 0.f;
        float t2 = lane < 8 ? sred[8 + lane] : 0.f;
        #pragma unroll
        for (int off = 4; off > 0; off >>= 1) {
            t1 += __shfl_down_sync(0xffffffffu, t1, off);
            t2 += __shfl_down_sync(0xffffffffu, t2, off);
        }
        if (lane == 0) {
            const float mu = t1 * (1.f / 1024.f);
            s_stats[0] = mu;
            s_stats[1] = rsqrtf(t2 * (1.f / 1024.f) - mu * mu + EPSf);
        }
    }
    __syncthreads();
    const float mu = s_stats[0], rs = s_stats[1];
    float cc[4];
    {
        const __nv_bfloat162 h01 = *(const __nv_bfloat162*)(g_cell_hi + base);
        const __nv_bfloat162 h23 = *(const __nv_bfloat162*)(g_cell_hi + base + 2);
        const __nv_bfloat162 l01 = *(const __nv_bfloat162*)(g_cell_lo + base);
        const __nv_bfloat162 l23 = *(const __nv_bfloat162*)(g_cell_lo + base + 2);
        cc[0] = __bfloat162float(h01.x) + __bfloat162float(l01.x);
        cc[1] = __bfloat162float(h01.y) + __bfloat162float(l01.y);
        cc[2] = __bfloat162float(h23.x) + __bfloat162float(l23.x);
        cc[3] = __bfloat162float(h23.y) + __bfloat162float(l23.y);
    }
    const float4 gg = *(const float4*)(gam + t * 4);
    const float4 bb = *(const float4*)(bet + t * 4);
    float4 o;
    o.x = cc[0] / (1.f + __expf(-((v.x - mu) * rs * gg.x + bb.x)));
    o.y = cc[1] / (1.f + __expf(-((v.y - mu) * rs * gg.y + bb.y)));
    o.z = cc[2] / (1.f + __expf(-((v.z - mu) * rs * gg.z + bb.z)));
    o.w = cc[3] / (1.f + __expf(-((v.w - mu) * rs * gg.w + bb.w)));
    *(float4*)(out + base) = o;
}

// =====================================================================
extern "C" void kernel_launch(void* const* d_in, const int* in_sizes, int n_in,
                              void* d_out, int out_size) {
    (void)in_sizes; (void)n_in; (void)out_size;
    const float* x       = (const float*)d_in[0];
    const float* W_hid   = (const float*)d_in[1];
    const float* b_hid   = (const float*)d_in[2];
    const float* g_cs    = (const float*)d_in[3];
    const float* be_cs   = (const float*)d_in[4];
    const float* g_hd    = (const float*)d_in[5];
    const float* be_hd   = (const float*)d_in[6];
    const float* W_og    = (const float*)d_in[7];
    const float* b_og    = (const float*)d_in[8];
    const float* g_ogp   = (const float*)d_in[9];
    const float* be_ogp  = (const float*)d_in[10];
    const float* init_cx = (const float*)d_in[11];
    float* out = (float*)d_out;

    cudaFuncSetAttribute(k_gemm_pipe<N1z, true>,
                         cudaFuncAttributeMaxDynamicSharedMemorySize, SM_TOT);
    cudaFuncSetAttribute(k_gemm_pipe<128, false>,
                         cudaFuncAttributeMaxDynamicSharedMemorySize, SM_TOT);

    // 1: Phase-1 partial sums + x split + weight conversion (fused)
    k_partial_wconv<<<dim3(Bz + 2, NCH), 1024>>>(x, W_hid, W_og);
    // 2: chunk offsets
    k_scan1_offsets<<<Bz, 1024>>>();
    // 3: cumsum LN -> csum hi/lo planes (batch-8 reductions)
    k_scan1_ln<<<dim3(Bz, NCH), 1024>>>(x, g_cs, be_cs);
    // 4: GEMM1 (n-major grid for L2 A-reuse)
    k_gemm_pipe<N1z, true><<<dim3(3, Sz * Bz / 128, Hz), 256, SM_TOT>>>(b_hid);
    // 5: gates (batch-8 reductions)
    k_gates<<<dim3(Bz, NCH), 1024>>>(g_hd, be_hd);
    // 6: carry
    k_carry<<<Bz, 1024>>>(init_cx);
    // 7: replay -> cell hi/lo planes
    k_replay<<<dim3(Bz, NCH), 1024>>>();
    // 8: GEMM2
    k_gemm_pipe<128, false><<<dim3(Sz * Bz / 128, 1, Hz), 256, SM_TOT>>>(b_og);
    // 9: final
    k_final<<<Bz * Sz, 256>>>(g_ogp, be_ogp, out);
}

// round 16
// speedup vs baseline: 1.0186x; 1.0186x over previous
#include <cuda_runtime.h>
#include <cuda_bf16.h>
#include <cstdint>

#define Bz   4
#define Sz   4096
#define Hz   8
#define Lz   1024      // H * DI
#define N1z  384       // 3 * DO
#define NCH  128       // chunks over S
#define CLEN 32        // S / NCH
#define EPSf 1e-6f

typedef unsigned long long u64;

// ---------------- scratch (static device memory; no allocations) ----------------
static __device__ float  g_h3[(size_t)Bz * Sz * Hz * N1z];       // 192 MB
static __device__ float2 g_fgi[(size_t)Bz * Sz * Lz];            // 128 MB (f, i)
static __device__ float  g_og[(size_t)Bz * Sz * Lz];             // 64 MB
static __device__ float  g_chA[Bz * NCH * Lz];
static __device__ float  g_chF[Bz * NCH * Lz];
static __device__ float  g_chAcc[Bz * NCH * Lz];
static __device__ float  g_carry[Bz * NCH * Lz];
// split-bf16 A-side operand planes, layout [m][h][k] (k fastest, 128 per head)
static __device__ __nv_bfloat16 g_x_hi[(size_t)Bz * Sz * Lz];
static __device__ __nv_bfloat16 g_x_lo[(size_t)Bz * Sz * Lz];
static __device__ __nv_bfloat16 g_csum_hi[(size_t)Bz * Sz * Lz];
static __device__ __nv_bfloat16 g_csum_lo[(size_t)Bz * Sz * Lz];
static __device__ __nv_bfloat16 g_cell_hi[(size_t)Bz * Sz * Lz];
static __device__ __nv_bfloat16 g_cell_lo[(size_t)Bz * Sz * Lz];
// split-bf16 weights, transposed to [h][n][k=256]
static __device__ __nv_bfloat16 g_Whid_hi[Hz * N1z * 256];
static __device__ __nv_bfloat16 g_Whid_lo[Hz * N1z * 256];
static __device__ __nv_bfloat16 g_Wog_hi[Hz * 128 * 256];
static __device__ __nv_bfloat16 g_Wog_lo[Hz * 128 * 256];

// ========================= asm helpers ==========================
__device__ __forceinline__ uint32_t smem_u32(const void* p) {
    uint32_t a;
    asm("{ .reg .u64 t; cvta.to.shared.u64 t, %1; cvt.u32.u64 %0, t; }"
        : "=r"(a) : "l"(p));
    return a;
}
__device__ __forceinline__ void ldsm4(uint32_t* r, uint32_t addr) {
    asm volatile("ldmatrix.sync.aligned.m8n8.x4.shared.b16 {%0,%1,%2,%3}, [%4];"
        : "=r"(r[0]), "=r"(r[1]), "=r"(r[2]), "=r"(r[3]) : "r"(addr));
}
__device__ __forceinline__ void mma16816(float* c, const uint32_t* a, const uint32_t* b) {
    asm volatile(
        "mma.sync.aligned.m16n8k16.row.col.f32.bf16.bf16.f32 "
        "{%0,%1,%2,%3}, {%4,%5,%6,%7}, {%8,%9}, {%0,%1,%2,%3};"
        : "+f"(c[0]), "+f"(c[1]), "+f"(c[2]), "+f"(c[3])
        : "r"(a[0]), "r"(a[1]), "r"(a[2]), "r"(a[3]), "r"(b[0]), "r"(b[1]));
}
__device__ __forceinline__ void cpa16(uint32_t dst, const void* src) {
    asm volatile("cp.async.cg.shared.global [%0], [%1], 16;" :: "r"(dst), "l"(src));
}
#define CP_COMMIT() asm volatile("cp.async.commit_group;")

// SW64 swizzle for 64-byte rows (conflict-free 8x16B ldmatrix)
__device__ __forceinline__ uint32_t swz64(uint32_t o) { return o ^ ((o >> 3) & 0x30); }

// stage layout: per stage 32KB = Ahi(8K) Alo(8K) Bhi(8K) Blo(8K); 3 stages = 96KB
#define STG(s)  ((s) * 32768)
#define P_AHI 0
#define P_ALO 8192
#define P_BHI 16384
#define P_BLO 24576
#define SM_TOT 98304

// =====================================================================
// Fused: Phase-1 chunk sums + x hi/lo split (single x read) | weight conv
// =====================================================================
__global__ void k_partial_wconv(const float* __restrict__ x,
                                const float* __restrict__ W_hid,
                                const float* __restrict__ W_og) {
    __shared__ __nv_bfloat16 smh[64][66];
    __shared__ __nv_bfloat16 sml[64][66];
    const int bx = blockIdx.x, by = blockIdx.y, tid = threadIdx.x;

    if (bx < Bz) {
        const size_t base = (size_t)(bx * Sz + by * CLEN) * Lz + tid;
        float s = 0.f;
        #pragma unroll 4
        for (int i = 0; i < CLEN; i++) {
            const float v = x[base + (size_t)i * Lz];
            s += v;
            const __nv_bfloat16 vh = __float2bfloat16(v);
            g_x_hi[base + (size_t)i * Lz] = vh;
            g_x_lo[base + (size_t)i * Lz] = __float2bfloat16(v - __bfloat162float(vh));
        }
        g_chA[(bx * NCH + by) * Lz + tid] = s;
        return;
    }

    // weight conversion tile
    const int t = (bx - Bz) * gridDim.y + by;   // 0..255
    const float* W;
    __nv_bfloat16 *hi, *lo;
    int N, h, kt, nt;
    if (t < 192) {
        W = W_hid; hi = g_Whid_hi; lo = g_Whid_lo; N = N1z;
        h = t / 24; const int r = t % 24; kt = r / 6; nt = r % 6;
    } else {
        const int t2 = t - 192;
        W = W_og; hi = g_Wog_hi; lo = g_Wog_lo; N = 128;
        h = t2 / 8; const int r = t2 % 8; kt = r / 2; nt = r % 2;
    }
    #pragma unroll
    for (int i = 0; i < 4; i++) {
        const int idx = tid + i * 1024;
        const int nl = idx & 63, kl = idx >> 6;
        const float v = W[(size_t)(h * 256 + kt * 64 + kl) * N + nt * 64 + nl];
        const __nv_bfloat16 vh = __float2bfloat16(v);
        smh[nl][kl] = vh;
        sml[nl][kl] = __float2bfloat16(v - __bfloat162float(vh));
    }
    __syncthreads();
    {
        const int nl = tid >> 4, k4 = (tid & 15) * 4;
        __nv_bfloat16 h4[4], l4[4];
        #pragma unroll
        for (int j = 0; j < 4; j++) { h4[j] = smh[nl][k4 + j]; l4[j] = sml[nl][k4 + j]; }
        const size_t o = (size_t)(h * N + nt * 64 + nl) * 256 + kt * 64 + k4;
        *(uint2*)(hi + o) = *(uint2*)h4;
        *(uint2*)(lo + o) = *(uint2*)l4;
    }
}

// =====================================================================
// Phase 1b: chunk-offset exclusive scan (MLP-batched loads)
// =====================================================================
__global__ void k_scan1_offsets() {
    const int b = blockIdx.x, l = threadIdx.x;
    float run = 0.f;
    #pragma unroll
    for (int g = 0; g < NCH; g += 16) {
        float v[16];
        #pragma unroll
        for (int j = 0; j < 16; j++)
            v[j] = g_chA[(b * NCH + g + j) * Lz + l];
        #pragma unroll
        for (int j = 0; j < 16; j++) {
            g_chA[(b * NCH + g + j) * Lz + l] = run;
            run += v[j];
        }
    }
}

// =====================================================================
// Phase 1c: cumsum + LN over 1024, batch-4 positions per reduction round
// =====================================================================
__global__ void k_scan1_ln(const float* __restrict__ x,
                           const float* __restrict__ gam,
                           const float* __restrict__ bet) {
    __shared__ float sred1[4][32];
    __shared__ float sred2[4][32];
    __shared__ float s_stats[4][2];
    const int b = blockIdx.x, ch = blockIdx.y, l = threadIdx.x;
    const int wid = l >> 5, lane = l & 31;
    float c = g_chA[(b * NCH + ch) * Lz + l];
    const float gv = gam[l], bv = bet[l];
    const size_t base = (size_t)(b * Sz + ch * CLEN) * Lz + l;

    for (int i0 = 0; i0 < CLEN; i0 += 4) {
        float xv[4], v[4];
        #pragma unroll
        for (int p = 0; p < 4; p++)
            xv[p] = x[base + (size_t)(i0 + p) * Lz];
        v[0] = c;
        v[1] = v[0] + xv[0];
        v[2] = v[1] + xv[1];
        v[3] = v[2] + xv[2];
        c    = v[3] + xv[3];

        float r1[4], r2[4];
        #pragma unroll
        for (int p = 0; p < 4; p++) { r1[p] = v[p]; r2[p] = v[p] * v[p]; }
        #pragma unroll
        for (int off = 16; off > 0; off >>= 1)
            #pragma unroll
            for (int p = 0; p < 4; p++) {
                r1[p] += __shfl_down_sync(0xffffffffu, r1[p], off);
                r2[p] += __shfl_down_sync(0xffffffffu, r2[p], off);
            }
        if (lane == 0)
            #pragma unroll
            for (int p = 0; p < 4; p++) { sred1[p][wid] = r1[p]; sred2[p][wid] = r2[p]; }
        __syncthreads();
        if (wid < 4) {
            float t1 = sred1[wid][lane], t2 = sred2[wid][lane];
            #pragma unroll
            for (int off = 16; off > 0; off >>= 1) {
                t1 += __shfl_down_sync(0xffffffffu, t1, off);
                t2 += __shfl_down_sync(0xffffffffu, t2, off);
            }
            if (lane == 0) {
                const float mu = t1 * (1.f / 1024.f);
                s_stats[wid][0] = mu;
                s_stats[wid][1] = rsqrtf(t2 * (1.f / 1024.f) - mu * mu + EPSf);
            }
        }
        __syncthreads();
        #pragma unroll
        for (int p = 0; p < 4; p++) {
            const float ov = (v[p] - s_stats[p][0]) * s_stats[p][1] * gv + bv;
            const __nv_bfloat16 oh = __float2bfloat16(ov);
            g_csum_hi[base + (size_t)(i0 + p) * Lz] = oh;
            g_csum_lo[base + (size_t)(i0 + p) * Lz] =
                __float2bfloat16(ov - __bfloat162float(oh));
        }
        __syncthreads();
    }
}

// =====================================================================
// Fully-async HMMA GEMM: K-chunks of 32, 3-stage cp.async ring (96KB),
// 2 CTAs/SM, single sync per chunk, term-major MMA ordering.
// PHASE1 grid: (n=3, m=128, h=8) so n-tile siblings sharing A run
// temporally adjacent -> A reads hit L2.  GEMM2 grid: (m, 1, h).
// =====================================================================
template <int NLD, bool PHASE1>
__global__ __launch_bounds__(256, 2) void k_gemm_pipe(const float* __restrict__ bias) {
    float* __restrict__ C = PHASE1 ? g_h3 : g_og;
    const __nv_bfloat16* __restrict__ Bhi = PHASE1 ? g_Whid_hi : g_Wog_hi;
    const __nv_bfloat16* __restrict__ Blo = PHASE1 ? g_Whid_lo : g_Wog_lo;
    const __nv_bfloat16* __restrict__ A1hi = PHASE1 ? g_csum_hi : g_cell_hi;
    const __nv_bfloat16* __restrict__ A1lo = PHASE1 ? g_csum_lo : g_cell_lo;

    extern __shared__ char sm[];
    const uint32_t sb = smem_u32(sm);
    const int tid = threadIdx.x;
    const int lane = tid & 31, wid = tid >> 5;
    const int m0 = (PHASE1 ? blockIdx.y : blockIdx.x) * 128;
    const int n0 = (PHASE1 ? blockIdx.x : blockIdx.y) * 128;
    const int h  = blockIdx.z;
    const int wm = (wid & 3) * 32;
    const int wn = (wid >> 2) * 64;

    float acc[2][8][4];
    #pragma unroll
    for (int mt = 0; mt < 2; mt++)
        #pragma unroll
        for (int nt = 0; nt < 8; nt++)
            #pragma unroll
            for (int q = 0; q < 4; q++) acc[mt][nt][q] = 0.f;

    const int aq = lane >> 3;
    const int arow_l = (aq & 1) * 8 + (lane & 7);
    const int akb    = (aq >> 1) * 16;
    const int brow_l = (aq >> 1) * 8 + (lane & 7);
    const int bkb    = (aq & 1) * 16;

    // stage s covers k elements [s*32, s*32+32); ring slot s%3
    #define ISSUE_STAGE(s) do {                                                    \
        const __nv_bfloat16* Ah = ((s) < 4) ? g_x_hi : A1hi;                       \
        const __nv_bfloat16* Al = ((s) < 4) ? g_x_lo : A1lo;                       \
        const int kA = ((s) & 3) * 32;                                             \
        const uint32_t stb = sb + STG((s) % 3);                                    \
        _Pragma("unroll")                                                          \
        for (int j = 0; j < 2; j++) {                                              \
            const int idx = tid + j * 256;                                         \
            const int row = idx >> 2, q = idx & 3;                                 \
            const uint32_t so = swz64((uint32_t)(row * 64 + q * 16));              \
            const size_t aoff = ((size_t)(m0 + row) * Hz + h) * 128 + kA + q * 8;  \
            cpa16(stb + P_AHI + so, Ah + aoff);                                    \
            cpa16(stb + P_ALO + so, Al + aoff);                                    \
            const size_t boff = ((size_t)(h * NLD + n0 + row) * 256 + (s) * 32 + q * 8); \
            cpa16(stb + P_BHI + so, Bhi + boff);                                   \
            cpa16(stb + P_BLO + so, Blo + boff);                                   \
        }                                                                          \
        CP_COMMIT();                                                               \
    } while (0)

    ISSUE_STAGE(0);
    ISSUE_STAGE(1);

    #pragma unroll 1
    for (int c = 0; c < 8; c++) {
        if (c < 7) asm volatile("cp.async.wait_group 1;");
        else       asm volatile("cp.async.wait_group 0;");
        __syncthreads();
        // slot (c+2)%3 == (c-1)%3: fully consumed by all warps before this sync
        if (c + 2 < 8) ISSUE_STAGE(c + 2);

        const uint32_t stb = sb + STG(c % 3);
        #pragma unroll
        for (int k16 = 0; k16 < 2; k16++) {
            uint32_t ahi[2][4], alo[2][4];
            #pragma unroll
            for (int mt = 0; mt < 2; mt++) {
                const uint32_t off =
                    swz64((uint32_t)((wm + mt * 16 + arow_l) * 64 + k16 * 32 + akb));
                ldsm4(ahi[mt], stb + P_AHI + off);
                ldsm4(alo[mt], stb + P_ALO + off);
            }
            #pragma unroll
            for (int np = 0; np < 4; np++) {
                uint32_t bhi[4], blo[4];
                const uint32_t off =
                    swz64((uint32_t)((wn + np * 16 + brow_l) * 64 + k16 * 32 + bkb));
                ldsm4(bhi, stb + P_BHI + off);
                ldsm4(blo, stb + P_BLO + off);
                // term-major: 4 independent accumulators between reuses
                float* a00 = acc[0][np * 2];
                float* a01 = acc[0][np * 2 + 1];
                float* a10 = acc[1][np * 2];
                float* a11 = acc[1][np * 2 + 1];
                mma16816(a00, ahi[0], bhi);
                mma16816(a01, ahi[0], bhi + 2);
                mma16816(a10, ahi[1], bhi);
                mma16816(a11, ahi[1], bhi + 2);
                mma16816(a00, alo[0], bhi);
                mma16816(a01, alo[0], bhi + 2);
                mma16816(a10, alo[1], bhi);
                mma16816(a11, alo[1], bhi + 2);
                mma16816(a00, ahi[0], blo);
                mma16816(a01, ahi[0], blo + 2);
                mma16816(a10, ahi[1], blo);
                mma16816(a11, ahi[1], blo + 2);
            }
        }
    }

    // ---- epilogue ----
    #pragma unroll
    for (int mt = 0; mt < 2; mt++) {
        const int r0 = m0 + wm + mt * 16 + (lane >> 2);
        #pragma unroll
        for (int nt = 0; nt < 8; nt++) {
            const int col = n0 + wn + nt * 8 + (lane & 3) * 2;
            const float2 bv = *(const float2*)(bias + h * NLD + col);
            float2 o0, o1;
            o0.x = acc[mt][nt][0] + bv.x;  o0.y = acc[mt][nt][1] + bv.y;
            o1.x = acc[mt][nt][2] + bv.x;  o1.y = acc[mt][nt][3] + bv.y;
            *(float2*)(C + ((size_t)r0 * Hz + h) * NLD + col)       = o0;
            *(float2*)(C + ((size_t)(r0 + 8) * Hz + h) * NLD + col) = o1;
        }
    }
    #undef ISSUE_STAGE
}

// =====================================================================
// Phase 3: LN over 3072 + gates + chunk composition, batch-4 positions
// =====================================================================
__global__ void k_gates(const float* __restrict__ gam, const float* __restrict__ bet) {
    __shared__ float sred1[4][32];
    __shared__ float sred2[4][32];
    __shared__ float s_stats[4][2];
    const int b = blockIdx.x, ch = blockIdx.y, l = threadIdx.x;
    const int wid = l >> 5, lane = l & 31;
    const int h = l >> 7, dd = l & 127;
    const int pb = (h * 3) * 128 + dd;
    const int rbase = h * N1z + dd;                 // channel of igate in row
    const float gi = gam[pb], gf = gam[pb + 128], gh = gam[pb + 256];
    const float bi = bet[pb], bf = bet[pb + 128], bh = bet[pb + 256];
    float F = 1.f, Acc = 0.f;

    for (int i0 = 0; i0 < CLEN; i0 += 4) {
        float vi[4], vf[4], vh[4];
        #pragma unroll
        for (int p = 0; p < 4; p++) {
            const size_t rb = (size_t)(b * Sz + ch * CLEN + i0 + p) * (Hz * N1z) + rbase;
            vi[p] = g_h3[rb];
            vf[p] = g_h3[rb + 128];
            vh[p] = g_h3[rb + 256];
        }
        float r1[4], r2[4];
        #pragma unroll
        for (int p = 0; p < 4; p++) {
            r1[p] = vi[p] + vf[p] + vh[p];
            r2[p] = vi[p] * vi[p] + vf[p] * vf[p] + vh[p] * vh[p];
        }
        #pragma unroll
        for (int off = 16; off > 0; off >>= 1)
            #pragma unroll
            for (int p = 0; p < 4; p++) {
                r1[p] += __shfl_down_sync(0xffffffffu, r1[p], off);
                r2[p] += __shfl_down_sync(0xffffffffu, r2[p], off);
            }
        if (lane == 0)
            #pragma unroll
            for (int p = 0; p < 4; p++) { sred1[p][wid] = r1[p]; sred2[p][wid] = r2[p]; }
        __syncthreads();
        if (wid < 4) {
            float t1 = sred1[wid][lane], t2 = sred2[wid][lane];
            #pragma unroll
            for (int off = 16; off > 0; off >>= 1) {
                t1 += __shfl_down_sync(0xffffffffu, t1, off);
                t2 += __shfl_down_sync(0xffffffffu, t2, off);
            }
            if (lane == 0) {
                const float mu = t1 * (1.f / 3072.f);
                s_stats[wid][0] = mu;
                s_stats[wid][1] = rsqrtf(t2 * (1.f / 3072.f) - mu * mu + EPSf);
            }
        }
        __syncthreads();
        #pragma unroll
        for (int p = 0; p < 4; p++) {
            const float mu = s_stats[p][0], rs = s_stats[p][1];
            const float xig = (vi[p] - mu) * rs * gi + bi;
            const float xfg = (vf[p] - mu) * rs * gf + bf;
            const float xhd = (vh[p] - mu) * rs * gh + bh;
            const float f  = 1.f / (1.f + __expf(-xfg));
            const float ii = (1.f / (1.f + __expf(-xig))) * fmaxf(xhd, 0.f);
            g_fgi[(size_t)(b * Sz + ch * CLEN + i0 + p) * Lz + l] = make_float2(f, ii);
            Acc = f * Acc + ii;
            F *= f;
        }
        __syncthreads();
    }
    const int ci = (b * NCH + ch) * Lz + l;
    g_chF[ci] = F;
    g_chAcc[ci] = Acc;
}

// =====================================================================
// Phase 4a: chunk-carry scan (MLP-batched loads)
// =====================================================================
__global__ void k_carry(const float* __restrict__ init_cx) {
    const int b = blockIdx.x, l = threadIdx.x;
    float c = init_cx[l];
    #pragma unroll
    for (int g = 0; g < NCH; g += 16) {
        float vf[16], va[16];
        #pragma unroll
        for (int j = 0; j < 16; j++) {
            const int idx = (b * NCH + g + j) * Lz + l;
            vf[j] = g_chF[idx];
            va[j] = g_chAcc[idx];
        }
        #pragma unroll
        for (int j = 0; j < 16; j++) {
            g_carry[(b * NCH + g + j) * Lz + l] = c;
            c = vf[j] * c + va[j];
        }
    }
}

// =====================================================================
// Phase 4b: replay scan, writing cell as split-bf16 planes
// =====================================================================
__global__ void k_replay() {
    const int b = blockIdx.x, ch = blockIdx.y, l = threadIdx.x;
    float c = g_carry[(b * NCH + ch) * Lz + l];
    const size_t base = (size_t)(b * Sz + ch * CLEN) * Lz + l;
    #pragma unroll 8
    for (int i = 0; i < CLEN; i++) {
        const float2 fi = g_fgi[base + (size_t)i * Lz];
        c = fi.x * c + fi.y;
        const __nv_bfloat16 chh = __float2bfloat16(c);
        g_cell_hi[base + (size_t)i * Lz] = chh;
        g_cell_lo[base + (size_t)i * Lz] = __float2bfloat16(c - __bfloat162float(chh));
    }
}

// =====================================================================
// Phase 5: LN over (H,DO) per (b,s), sigmoid(og) * cell -> out
// =====================================================================
__global__ void k_final(const float* __restrict__ gam, const float* __restrict__ bet,
                        float* __restrict__ out) {
    __shared__ float sred[16];
    __shared__ float s_stats[2];
    const int bs = blockIdx.x, t = threadIdx.x;
    const int wid = t >> 5, lane = t & 31;
    const size_t base = (size_t)bs * Lz + t * 4;
    const float4 v = *(const float4*)(g_og + base);
    float r1 = v.x + v.y + v.z + v.w;
    float r2 = v.x * v.x + v.y * v.y + v.z * v.z + v.w * v.w;
    #pragma unroll
    for (int off = 16; off > 0; off >>= 1) {
        r1 += __shfl_down_sync(0xffffffffu, r1, off);
        r2 += __shfl_down_sync(0xffffffffu, r2, off);
    }
    if (lane == 0) { sred[wid] = r1; sred[8 + wid] = r2; }
    __syncthreads();
    if (wid == 0) {
        float t1 = lane < 8 ? sred[lane] : 0.f;
        float t2 = lane < 8 ? sred[8 + lane] : 0.f;
        #pragma unroll
        for (int off = 4; off > 0; off >>= 1) {
            t1 += __shfl_down_sync(0xffffffffu, t1, off);
            t2 += __shfl_down_sync(0xffffffffu, t2, off);
        }
        if (lane == 0) {
            const float mu = t1 * (1.f / 1024.f);
            s_stats[0] = mu;
            s_stats[1] = rsqrtf(t2 * (1.f / 1024.f) - mu * mu + EPSf);
        }
    }
    __syncthreads();
    const float mu = s_stats[0], rs = s_stats[1];
    float cc[4];
    {
        const __nv_bfloat162 h01 = *(const __nv_bfloat162*)(g_cell_hi + base);
        const __nv_bfloat162 h23 = *(const __nv_bfloat162*)(g_cell_hi + base + 2);
        const __nv_bfloat162 l01 = *(const __nv_bfloat162*)(g_cell_lo + base);
        const __nv_bfloat162 l23 = *(const __nv_bfloat162*)(g_cell_lo + base + 2);
        cc[0] = __bfloat162float(h01.x) + __bfloat162float(l01.x);
        cc[1] = __bfloat162float(h01.y) + __bfloat162float(l01.y);
        cc[2] = __bfloat162float(h23.x) + __bfloat162float(l23.x);
        cc[3] = __bfloat162float(h23.y) + __bfloat162float(l23.y);
    }
    const float4 gg = *(const float4*)(gam + t * 4);
    const float4 bb = *(const float4*)(bet + t * 4);
    float4 o;
    o.x = cc[0] / (1.f + __expf(-((v.x - mu) * rs * gg.x + bb.x)));
    o.y = cc[1] / (1.f + __expf(-((v.y - mu) * rs * gg.y + bb.y)));
    o.z = cc[2] / (1.f + __expf(-((v.z - mu) * rs * gg.z + bb.z)));
    o.w = cc[3] / (1.f + __expf(-((v.w - mu) * rs * gg.w + bb.w)));
    *(float4*)(out + base) = o;
}

// =====================================================================
extern "C" void kernel_launch(void* const* d_in, const int* in_sizes, int n_in,
                              void* d_out, int out_size) {
    (void)in_sizes; (void)n_in; (void)out_size;
    const float* x       = (const float*)d_in[0];
    const float* W_hid   = (const float*)d_in[1];
    const float* b_hid   = (const float*)d_in[2];
    const float* g_cs    = (const float*)d_in[3];
    const float* be_cs   = (const float*)d_in[4];
    const float* g_hd    = (const float*)d_in[5];
    const float* be_hd   = (const float*)d_in[6];
    const float* W_og    = (const float*)d_in[7];
    const float* b_og    = (const float*)d_in[8];
    const float* g_ogp   = (const float*)d_in[9];
    const float* be_ogp  = (const float*)d_in[10];
    const float* init_cx = (const float*)d_in[11];
    float* out = (float*)d_out;

    cudaFuncSetAttribute(k_gemm_pipe<N1z, true>,
                         cudaFuncAttributeMaxDynamicSharedMemorySize, SM_TOT);
    cudaFuncSetAttribute(k_gemm_pipe<128, false>,
                         cudaFuncAttributeMaxDynamicSharedMemorySize, SM_TOT);

    // 1: Phase-1 partial sums + x split + weight conversion (fused)
    k_partial_wconv<<<dim3(Bz + 2, NCH), 1024>>>(x, W_hid, W_og);
    // 2: chunk offsets
    k_scan1_offsets<<<Bz, 1024>>>();
    // 3: cumsum LN -> csum hi/lo planes (batch-4 reductions)
    k_scan1_ln<<<dim3(Bz, NCH), 1024>>>(x, g_cs, be_cs);
    // 4: GEMM1 (n-major grid for L2 A-reuse)
    k_gemm_pipe<N1z, true><<<dim3(3, Sz * Bz / 128, Hz), 256, SM_TOT>>>(b_hid);
    // 5: gates (batch-4 reductions)
    k_gates<<<dim3(Bz, NCH), 1024>>>(g_hd, be_hd);
    // 6: carry
    k_carry<<<Bz, 1024>>>(init_cx);
    // 7: replay -> cell hi/lo planes
    k_replay<<<dim3(Bz, NCH), 1024>>>();
    // 8: GEMM2
    k_gemm_pipe<128, false><<<dim3(Sz * Bz / 128, 1, Hz), 256, SM_TOT>>>(b_og);
    // 9: final
    k_final<<<Bz * Sz, 256>>>(g_ogp, be_ogp, out);
}